// round 11
// baseline (speedup 1.0000x reference)
#include <cuda_runtime.h>
#include <cstdint>

#define LSEQ   2048
#define DMODEL 1024
#define NH     16
#define DKH    64
#define NHOPS  3

typedef unsigned long long u64t;

__device__ __forceinline__ void f2unpack(float& lo, float& hi, u64t v) {
    asm("mov.b64 {%0, %1}, %2;" : "=f"(lo), "=f"(hi) : "l"(v));
}
__device__ __forceinline__ void ffma2(u64t& d, u64t a, u64t b) {
    asm("fma.rn.f32x2 %0, %1, %2, %0;" : "+l"(d) : "l"(a), "l"(b));
}

__device__ float g_Q[LSEQ * DMODEL];
__device__ float g_K[LSEQ * DMODEL];
__device__ float g_V[LSEQ * DMODEL];
__device__ float g_ctx[LSEQ * DMODEL];
__device__ float g_cur[LSEQ * DMODEL];
__device__ float g_gate[LSEQ];

// ---------------------------------------------------------------------------
// Projection GEMM: C[2048][1024] = A @ B + bias.
// 128x128 tile, BK=16, 256 threads, double-buffered smem, dup-B (pack-free).
// ---------------------------------------------------------------------------
__global__ __launch_bounds__(256)
void gemm_proj(const float* __restrict__ A, const float* __restrict__ B,
               const float* __restrict__ bias, float* __restrict__ C)
{
    extern __shared__ float sm[];
    float* As_ = sm;                  // [2][16][132]
    float* Bs_ = sm + 2 * 16 * 132;   // [2][16][260] (duplicated cols)

    const int tid = threadIdx.x;
    const int tx = tid & 15, ty = tid >> 4;
    const int rowBase = blockIdx.y * 128, colBase = blockIdx.x * 128;

    const int ar = tid >> 1, akg = (tid & 1) * 8;
    const int bkr = tid >> 4, bcg = (tid & 15) * 8;

    const float* Ap = A + (size_t)(rowBase + ar) * DMODEL + akg;
    const float* Bp = B + (size_t)bkr * DMODEL + colBase + bcg;

    u64t acc[4][8];
#pragma unroll
    for (int p = 0; p < 4; p++)
#pragma unroll
        for (int j = 0; j < 8; j++) acc[p][j] = 0ull;

    float4 a0 = *(const float4*)Ap;
    float4 a1 = *(const float4*)(Ap + 4);
    float4 b0 = *(const float4*)Bp;
    float4 b1 = *(const float4*)(Bp + 4);

    {
        float* As = As_;
        As[(akg + 0) * 132 + ar] = a0.x; As[(akg + 1) * 132 + ar] = a0.y;
        As[(akg + 2) * 132 + ar] = a0.z; As[(akg + 3) * 132 + ar] = a0.w;
        As[(akg + 4) * 132 + ar] = a1.x; As[(akg + 5) * 132 + ar] = a1.y;
        As[(akg + 6) * 132 + ar] = a1.z; As[(akg + 7) * 132 + ar] = a1.w;
        float* Bs = Bs_ + bkr * 260 + 2 * bcg;
        *(float4*)&Bs[0]  = make_float4(b0.x, b0.x, b0.y, b0.y);
        *(float4*)&Bs[4]  = make_float4(b0.z, b0.z, b0.w, b0.w);
        *(float4*)&Bs[8]  = make_float4(b1.x, b1.x, b1.y, b1.y);
        *(float4*)&Bs[12] = make_float4(b1.z, b1.z, b1.w, b1.w);
    }
    __syncthreads();

    const int NT = DMODEL / 16;  // 64
    for (int kt = 0; kt < NT; kt++) {
        if (kt + 1 < NT) {
            a0 = *(const float4*)(Ap + (kt + 1) * 16);
            a1 = *(const float4*)(Ap + (kt + 1) * 16 + 4);
            b0 = *(const float4*)(Bp + (size_t)(kt + 1) * 16 * DMODEL);
            b1 = *(const float4*)(Bp + (size_t)(kt + 1) * 16 * DMODEL + 4);
        }
        const float* As = As_ + (kt & 1) * (16 * 132);
        const float* Bs = Bs_ + (kt & 1) * (16 * 260);
#pragma unroll
        for (int k = 0; k < 16; k++) {
            const u64t* pa0 = (const u64t*)&As[k * 132 + ty * 4];
            const u64t* pa1 = (const u64t*)&As[k * 132 + 64 + ty * 4];
            u64t ap[4] = {pa0[0], pa0[1], pa1[0], pa1[1]};
            const u64t* pb0 = (const u64t*)&Bs[k * 260 + tx * 8];
            const u64t* pb1 = (const u64t*)&Bs[k * 260 + 128 + tx * 8];
            u64t bp[8] = {pb0[0], pb0[1], pb0[2], pb0[3],
                          pb1[0], pb1[1], pb1[2], pb1[3]};
#pragma unroll
            for (int p = 0; p < 4; p++)
#pragma unroll
                for (int j = 0; j < 8; j++)
                    ffma2(acc[p][j], ap[p], bp[j]);
        }
        if (kt + 1 < NT) {
            float* As2 = As_ + ((kt + 1) & 1) * (16 * 132);
            float* Bs2 = Bs_ + ((kt + 1) & 1) * (16 * 260);
            As2[(akg + 0) * 132 + ar] = a0.x; As2[(akg + 1) * 132 + ar] = a0.y;
            As2[(akg + 2) * 132 + ar] = a0.z; As2[(akg + 3) * 132 + ar] = a0.w;
            As2[(akg + 4) * 132 + ar] = a1.x; As2[(akg + 5) * 132 + ar] = a1.y;
            As2[(akg + 6) * 132 + ar] = a1.z; As2[(akg + 7) * 132 + ar] = a1.w;
            float* Bd = Bs2 + bkr * 260 + 2 * bcg;
            *(float4*)&Bd[0]  = make_float4(b0.x, b0.x, b0.y, b0.y);
            *(float4*)&Bd[4]  = make_float4(b0.z, b0.z, b0.w, b0.w);
            *(float4*)&Bd[8]  = make_float4(b1.x, b1.x, b1.y, b1.y);
            *(float4*)&Bd[12] = make_float4(b1.z, b1.z, b1.w, b1.w);
            __syncthreads();
        }
    }

    const int c0 = colBase + tx * 4, c1 = colBase + 64 + tx * 4;
    float4 bv0 = *(const float4*)&bias[c0];
    float4 bv1 = *(const float4*)&bias[c1];
#pragma unroll
    for (int p = 0; p < 4; p++) {
        float lo[8], hi[8];
#pragma unroll
        for (int j = 0; j < 8; j++) f2unpack(lo[j], hi[j], acc[p][j]);
        int r0 = rowBase + ((p < 2) ? (ty * 4 + p * 2) : (64 + ty * 4 + (p - 2) * 2));
        *(float4*)&C[(size_t)r0 * DMODEL + c0] =
            make_float4(lo[0] + bv0.x, lo[1] + bv0.y, lo[2] + bv0.z, lo[3] + bv0.w);
        *(float4*)&C[(size_t)r0 * DMODEL + c1] =
            make_float4(lo[4] + bv1.x, lo[5] + bv1.y, lo[6] + bv1.z, lo[7] + bv1.w);
        *(float4*)&C[(size_t)(r0 + 1) * DMODEL + c0] =
            make_float4(hi[0] + bv0.x, hi[1] + bv0.y, hi[2] + bv0.z, hi[3] + bv0.w);
        *(float4*)&C[(size_t)(r0 + 1) * DMODEL + c1] =
            make_float4(hi[4] + bv1.x, hi[5] + bv1.y, hi[6] + bv1.z, hi[7] + bv1.w);
    }
}

// ---------------------------------------------------------------------------
// Scores: S[h][q][k] = 0.125 * dot(cur, K). 128x128 tile, K=64, dup-B smem.
// ---------------------------------------------------------------------------
__global__ __launch_bounds__(256)
void scores_kernel(const float* __restrict__ Qc, const float* __restrict__ Kc,
                   float* __restrict__ S)
{
    extern __shared__ float sm[];
    float* As = sm;               // [64][132]  (dkh, qrow)
    float* Bs = sm + 64 * 132;    // [64][260]  (dkh, keyrow duplicated)

    const int tid = threadIdx.x;
    const int tx = tid & 15, ty = tid >> 4;
    const int h = blockIdx.z;
    const int qBase = blockIdx.y * 128, kBase = blockIdx.x * 128;

    const float* Ap = Qc + (size_t)qBase * DMODEL + h * DKH;
    const float* Bp = Kc + (size_t)kBase * DMODEL + h * DKH;

#pragma unroll
    for (int i = 0; i < 8; i++) {
        int idx = tid + i * 256;
        int r = idx >> 4, c4 = (idx & 15) * 4;
        float4 a = *(const float4*)(Ap + (size_t)r * DMODEL + c4);
        As[(c4 + 0) * 132 + r] = a.x; As[(c4 + 1) * 132 + r] = a.y;
        As[(c4 + 2) * 132 + r] = a.z; As[(c4 + 3) * 132 + r] = a.w;
        float4 b = *(const float4*)(Bp + (size_t)r * DMODEL + c4);
        *(float2*)&Bs[(c4 + 0) * 260 + 2 * r] = make_float2(b.x, b.x);
        *(float2*)&Bs[(c4 + 1) * 260 + 2 * r] = make_float2(b.y, b.y);
        *(float2*)&Bs[(c4 + 2) * 260 + 2 * r] = make_float2(b.z, b.z);
        *(float2*)&Bs[(c4 + 3) * 260 + 2 * r] = make_float2(b.w, b.w);
    }
    __syncthreads();

    u64t acc[4][8];
#pragma unroll
    for (int p = 0; p < 4; p++)
#pragma unroll
        for (int j = 0; j < 8; j++) acc[p][j] = 0ull;

#pragma unroll 4
    for (int k = 0; k < 64; k++) {
        const u64t* pa0 = (const u64t*)&As[k * 132 + ty * 4];
        const u64t* pa1 = (const u64t*)&As[k * 132 + 64 + ty * 4];
        u64t ap[4] = {pa0[0], pa0[1], pa1[0], pa1[1]};
        const u64t* pb0 = (const u64t*)&Bs[k * 260 + tx * 8];
        const u64t* pb1 = (const u64t*)&Bs[k * 260 + 128 + tx * 8];
        u64t bp[8] = {pb0[0], pb0[1], pb0[2], pb0[3],
                      pb1[0], pb1[1], pb1[2], pb1[3]};
#pragma unroll
        for (int p = 0; p < 4; p++)
#pragma unroll
            for (int j = 0; j < 8; j++)
                ffma2(acc[p][j], ap[p], bp[j]);
    }

    const float sc = 0.125f;
    float* Sp = S + ((size_t)(h * LSEQ + qBase)) * LSEQ + kBase;
#pragma unroll
    for (int p = 0; p < 4; p++) {
        float lo[8], hi[8];
#pragma unroll
        for (int j = 0; j < 8; j++) f2unpack(lo[j], hi[j], acc[p][j]);
        int r0 = (p < 2) ? (ty * 4 + p * 2) : (64 + ty * 4 + (p - 2) * 2);
        float* d0 = &Sp[(size_t)r0 * LSEQ];
        float* d1 = &Sp[(size_t)(r0 + 1) * LSEQ];
        *(float4*)&d0[tx * 4] =
            make_float4(lo[0] * sc, lo[1] * sc, lo[2] * sc, lo[3] * sc);
        *(float4*)&d0[64 + tx * 4] =
            make_float4(lo[4] * sc, lo[5] * sc, lo[6] * sc, lo[7] * sc);
        *(float4*)&d1[tx * 4] =
            make_float4(hi[0] * sc, hi[1] * sc, hi[2] * sc, hi[3] * sc);
        *(float4*)&d1[64 + tx * 4] =
            make_float4(hi[4] * sc, hi[5] * sc, hi[6] * sc, hi[7] * sc);
    }
}

// ---------------------------------------------------------------------------
// Row stats: one warp per (h,q) row in registers. Computes m, sum, then
// writes FINAL w = exp(s-m) * gate/sum in place (ctx becomes pure GEMM).
// ---------------------------------------------------------------------------
__global__ __launch_bounds__(256)
void stats_kernel(float* __restrict__ S)
{
    const int warp = threadIdx.x >> 5;
    const int lane = threadIdx.x & 31;
    const int row = blockIdx.x * 8 + warp;
    float* p = S + (size_t)row * LSEQ;

    float4 vals[16];
    float m = -1e30f;
#pragma unroll
    for (int i = 0; i < 16; i++) {
        vals[i] = *(const float4*)&p[(lane + i * 32) * 4];
        m = fmaxf(m, fmaxf(fmaxf(vals[i].x, vals[i].y), fmaxf(vals[i].z, vals[i].w)));
    }
#pragma unroll
    for (int off = 16; off > 0; off >>= 1)
        m = fmaxf(m, __shfl_xor_sync(0xffffffffu, m, off));

    float s = 0.f;
#pragma unroll
    for (int i = 0; i < 16; i++) {
        vals[i].x = __expf(vals[i].x - m);
        vals[i].y = __expf(vals[i].y - m);
        vals[i].z = __expf(vals[i].z - m);
        vals[i].w = __expf(vals[i].w - m);
        s += vals[i].x + vals[i].y + vals[i].z + vals[i].w;
    }
#pragma unroll
    for (int off = 16; off > 0; off >>= 1)
        s += __shfl_xor_sync(0xffffffffu, s, off);

    const float g = g_gate[row & (LSEQ - 1)] / s;
#pragma unroll
    for (int i = 0; i < 16; i++) {
        float4 w = {vals[i].x * g, vals[i].y * g, vals[i].z * g, vals[i].w * g};
        *(float4*)&p[(lane + i * 32) * 4] = w;
    }
}

// ---------------------------------------------------------------------------
// ctx = w @ V (pure GEMM). 128q x 64d per block, BK=32, double-buffered,
// dup-V smem, 1 sync/iter.
// ---------------------------------------------------------------------------
__global__ __launch_bounds__(256)
void ctx_kernel(const float* __restrict__ S, const float* __restrict__ V)
{
    extern __shared__ float sm[];
    float* Ws_ = sm;                  // [2][32][132] (k, qrow)
    float* Vs_ = sm + 2 * 32 * 132;   // [2][32][132] (k, dcol duplicated)

    const int tid = threadIdx.x;
    const int tx = tid & 15, ty = tid >> 4;
    const int h = blockIdx.y;
    const int qBase = blockIdx.x * 128;

    const float* Sbase = S + ((size_t)(h * LSEQ + qBase)) * LSEQ;
    const float* Vp = V + h * DKH;

    const int wr = tid >> 3, wcg = (tid & 7) * 4;   // W: 128 rows x 32 k
    const int vr = tid >> 4, vc = (tid & 15) * 4;   // V: 32 k x 64 d

    u64t acc[4][4];
#pragma unroll
    for (int p = 0; p < 4; p++)
#pragma unroll
        for (int j = 0; j < 4; j++) acc[p][j] = 0ull;

    float4 wreg[4], vreg[2];
#pragma unroll
    for (int i = 0; i < 4; i++) {
        int idx = tid + i * 256;
        int r = idx >> 3, cg = (idx & 7) * 4;
        wreg[i] = *(const float4*)&Sbase[(size_t)r * LSEQ + cg];
    }
#pragma unroll
    for (int i = 0; i < 2; i++) {
        int idx = tid + i * 256;
        int r = idx >> 4, c = (idx & 15) * 4;
        vreg[i] = *(const float4*)&Vp[(size_t)r * DMODEL + c];
    }
    {
        float* Ws = Ws_;
        float* Vs = Vs_;
#pragma unroll
        for (int i = 0; i < 4; i++) {
            int idx = tid + i * 256;
            int r = idx >> 3, cg = (idx & 7) * 4;
            Ws[(cg + 0) * 132 + r] = wreg[i].x; Ws[(cg + 1) * 132 + r] = wreg[i].y;
            Ws[(cg + 2) * 132 + r] = wreg[i].z; Ws[(cg + 3) * 132 + r] = wreg[i].w;
        }
#pragma unroll
        for (int i = 0; i < 2; i++) {
            int idx = tid + i * 256;
            int r = idx >> 4, c = (idx & 15) * 4;
            float* d = &Vs[r * 132 + 2 * c];
            *(float4*)&d[0] = make_float4(vreg[i].x, vreg[i].x, vreg[i].y, vreg[i].y);
            *(float4*)&d[4] = make_float4(vreg[i].z, vreg[i].z, vreg[i].w, vreg[i].w);
        }
    }
    __syncthreads();

    const int NT = LSEQ / 32;  // 64
    for (int kt = 0; kt < NT; kt++) {
        if (kt + 1 < NT) {
#pragma unroll
            for (int i = 0; i < 4; i++) {
                int idx = tid + i * 256;
                int r = idx >> 3, cg = (idx & 7) * 4;
                wreg[i] = *(const float4*)&Sbase[(size_t)r * LSEQ + (kt + 1) * 32 + cg];
            }
#pragma unroll
            for (int i = 0; i < 2; i++) {
                int idx = tid + i * 256;
                int r = idx >> 4, c = (idx & 15) * 4;
                vreg[i] = *(const float4*)&Vp[(size_t)((kt + 1) * 32 + r) * DMODEL + c];
            }
        }
        const float* Ws = Ws_ + (kt & 1) * (32 * 132);
        const float* Vs = Vs_ + (kt & 1) * (32 * 132);
#pragma unroll 8
        for (int k = 0; k < 32; k++) {
            const u64t* pa0 = (const u64t*)&Ws[k * 132 + ty * 4];
            const u64t* pa1 = (const u64t*)&Ws[k * 132 + 64 + ty * 4];
            u64t ap[4] = {pa0[0], pa0[1], pa1[0], pa1[1]};
            const u64t* pb = (const u64t*)&Vs[k * 132 + tx * 8];
            u64t bp[4] = {pb[0], pb[1], pb[2], pb[3]};
#pragma unroll
            for (int p = 0; p < 4; p++)
#pragma unroll
                for (int j = 0; j < 4; j++)
                    ffma2(acc[p][j], ap[p], bp[j]);
        }
        if (kt + 1 < NT) {
            float* Ws2 = Ws_ + ((kt + 1) & 1) * (32 * 132);
            float* Vs2 = Vs_ + ((kt + 1) & 1) * (32 * 132);
#pragma unroll
            for (int i = 0; i < 4; i++) {
                int idx = tid + i * 256;
                int r = idx >> 3, cg = (idx & 7) * 4;
                Ws2[(cg + 0) * 132 + r] = wreg[i].x; Ws2[(cg + 1) * 132 + r] = wreg[i].y;
                Ws2[(cg + 2) * 132 + r] = wreg[i].z; Ws2[(cg + 3) * 132 + r] = wreg[i].w;
            }
#pragma unroll
            for (int i = 0; i < 2; i++) {
                int idx = tid + i * 256;
                int r = idx >> 4, c = (idx & 15) * 4;
                float* d = &Vs2[r * 132 + 2 * c];
                *(float4*)&d[0] = make_float4(vreg[i].x, vreg[i].x, vreg[i].y, vreg[i].y);
                *(float4*)&d[4] = make_float4(vreg[i].z, vreg[i].z, vreg[i].w, vreg[i].w);
            }
            __syncthreads();
        }
    }

#pragma unroll
    for (int p = 0; p < 4; p++) {
        float lo[4], hi[4];
#pragma unroll
        for (int j = 0; j < 4; j++) f2unpack(lo[j], hi[j], acc[p][j]);
        int r0 = qBase + ((p < 2) ? (ty * 4 + p * 2) : (64 + ty * 4 + (p - 2) * 2));
        *(float4*)&g_ctx[(size_t)r0 * DMODEL + h * DKH + tx * 4] =
            make_float4(lo[0], lo[1], lo[2], lo[3]);
        *(float4*)&g_ctx[(size_t)(r0 + 1) * DMODEL + h * DKH + tx * 4] =
            make_float4(hi[0], hi[1], hi[2], hi[3]);
    }
}

// ---------------------------------------------------------------------------
__global__ __launch_bounds__(256)
void gates_kernel(const float* __restrict__ q, const float* __restrict__ Wg,
                  const float* __restrict__ bg)
{
    const int warp = threadIdx.x >> 5;
    const int lane = threadIdx.x & 31;
    const int row = blockIdx.x * 8 + warp;
    const float* p = q + (size_t)row * DMODEL;

    float s = 0.f;
#pragma unroll
    for (int i = 0; i < 8; i++) {
        float4 a = *(const float4*)&p[(lane + i * 32) * 4];
        float4 w = *(const float4*)&Wg[(lane + i * 32) * 4];
        s += a.x * w.x + a.y * w.y + a.z * w.z + a.w * w.w;
    }
#pragma unroll
    for (int off = 16; off > 0; off >>= 1)
        s += __shfl_xor_sync(0xffffffffu, s, off);

    if (lane == 0)
        g_gate[row] = 1.f / (1.f + __expf(-(s + bg[0])));
}

// ---------------------------------------------------------------------------
extern "C" void kernel_launch(void* const* d_in, const int* in_sizes, int n_in,
                              void* d_out, int out_size)
{
    const float* q  = (const float*)d_in[0];
    const float* k  = (const float*)d_in[1];
    const float* v  = (const float*)d_in[2];
    const float* Wq = (const float*)d_in[3];
    const float* bq = (const float*)d_in[4];
    const float* Wk = (const float*)d_in[5];
    const float* bk = (const float*)d_in[6];
    const float* Wv = (const float*)d_in[7];
    const float* bv = (const float*)d_in[8];
    const float* Wo = (const float*)d_in[9];
    const float* bo = (const float*)d_in[10];
    const float* Wg = (const float*)d_in[11];
    const float* bg = (const float*)d_in[12];
    const float* Wp = (const float*)d_in[13];
    const float* bp = (const float*)d_in[14];
    (void)in_sizes; (void)n_in; (void)out_size;

    float* out  = (float*)d_out;
    float* Wout = out + (size_t)LSEQ * DMODEL;

    float *pQ, *pK, *pV, *pCtx, *pCur;
    cudaGetSymbolAddress((void**)&pQ,   g_Q);
    cudaGetSymbolAddress((void**)&pK,   g_K);
    cudaGetSymbolAddress((void**)&pV,   g_V);
    cudaGetSymbolAddress((void**)&pCtx, g_ctx);
    cudaGetSymbolAddress((void**)&pCur, g_cur);

    const int smemGemm   = (2 * 16 * 132 + 2 * 16 * 260) * 4;  // 50176
    const int smemScores = (64 * 132 + 64 * 260) * 4;          // 100352
    const int smemCtx    = (2 * 32 * 132 * 2) * 4;             // 67584
    cudaFuncSetAttribute(gemm_proj, cudaFuncAttributeMaxDynamicSharedMemorySize, smemGemm);
    cudaFuncSetAttribute(scores_kernel, cudaFuncAttributeMaxDynamicSharedMemorySize, smemScores);
    cudaFuncSetAttribute(ctx_kernel, cudaFuncAttributeMaxDynamicSharedMemorySize, smemCtx);

    dim3 gProj(DMODEL / 128, LSEQ / 128);  // (8, 16)

    gates_kernel<<<LSEQ / 8, 256>>>(q, Wg, bg);
    gemm_proj<<<gProj, 256, smemGemm>>>(q, Wq, bq, pQ);
    gemm_proj<<<gProj, 256, smemGemm>>>(k, Wk, bk, pK);
    gemm_proj<<<gProj, 256, smemGemm>>>(v, Wv, bv, pV);

    const float* cur = pQ;
    for (int hop = 0; hop < NHOPS; hop++) {
        float* Sh = Wout + (size_t)hop * NH * LSEQ * LSEQ;
        dim3 gS(LSEQ / 128, LSEQ / 128, NH);
        scores_kernel<<<gS, 256, smemScores>>>(cur, pK, Sh);
        stats_kernel<<<NH * LSEQ / 8, 256>>>(Sh);
        dim3 gC(LSEQ / 128, NH);
        ctx_kernel<<<gC, 256, smemCtx>>>(Sh, pV);
        if (hop < NHOPS - 1) {
            gemm_proj<<<gProj, 256, smemGemm>>>(pCtx, Wp, bp, pCur);
            cur = pCur;
        }
    }
    gemm_proj<<<gProj, 256, smemGemm>>>(pCtx, Wo, bo, out);
}

// round 12
// speedup vs baseline: 1.7164x; 1.7164x over previous
#include <cuda_runtime.h>
#include <cstdint>

#define LSEQ   2048
#define DMODEL 1024
#define NH     16
#define DKH    64
#define NHOPS  3

typedef unsigned long long u64t;

// ---------------- f32x2 helpers (sm_100+ packed fp32, base ISA) ------------
__device__ __forceinline__ u64t f2pack(float lo, float hi) {
    u64t r; asm("mov.b64 %0, {%1, %2};" : "=l"(r) : "f"(lo), "f"(hi)); return r;
}
__device__ __forceinline__ void f2unpack(float& lo, float& hi, u64t v) {
    asm("mov.b64 {%0, %1}, %2;" : "=f"(lo), "=f"(hi) : "l"(v));
}
__device__ __forceinline__ void ffma2(u64t& d, u64t a, u64t b) {
    asm("fma.rn.f32x2 %0, %1, %2, %0;" : "+l"(d) : "l"(a), "l"(b));
}

// ---------------------------------------------------------------------------
// Scratch
// ---------------------------------------------------------------------------
__device__ float g_Q[LSEQ * DMODEL];
__device__ float g_K[LSEQ * DMODEL];
__device__ float g_V[LSEQ * DMODEL];
__device__ float g_ctx[LSEQ * DMODEL];
__device__ float g_cur[LSEQ * DMODEL];
__device__ float g_gate[LSEQ];

// ---------------------------------------------------------------------------
// Projection GEMM (R9 exact shape: 128x64, BK=8, 256 thr, 75 regs, pipe-sat).
// ---------------------------------------------------------------------------
__global__ __launch_bounds__(256)
void gemm_proj(const float* __restrict__ A, const float* __restrict__ B,
               const float* __restrict__ bias, float* __restrict__ C)
{
    __shared__ float As[8][132];
    __shared__ float Bs[8][64];

    const int tid = threadIdx.x;
    const int tx  = tid & 15;
    const int ty  = tid >> 4;
    const int rowBase = blockIdx.y * 128;
    const int colBase = blockIdx.x * 64;

    const int aRow = tid >> 1;
    const int aCol = (tid & 1) * 4;
    const int bRow = tid >> 5;
    const int bCol = (tid & 31) * 2;

    const float* Aptr = A + (size_t)(rowBase + aRow) * DMODEL + aCol;
    const float* Bptr = B + (size_t)bRow * DMODEL + colBase + bCol;

    u64t accp[4][4];
#pragma unroll
    for (int p = 0; p < 4; p++)
#pragma unroll
        for (int j = 0; j < 4; j++) accp[p][j] = 0ull;

    float4 aReg = *(const float4*)Aptr;
    float2 bReg = *(const float2*)Bptr;

    const int NT = DMODEL / 8;
    for (int kt = 0; kt < NT; kt++) {
        As[aCol + 0][aRow] = aReg.x; As[aCol + 1][aRow] = aReg.y;
        As[aCol + 2][aRow] = aReg.z; As[aCol + 3][aRow] = aReg.w;
        *(float2*)&Bs[bRow][bCol] = bReg;
        __syncthreads();
        if (kt + 1 < NT) {
            aReg = *(const float4*)(Aptr + (kt + 1) * 8);
            bReg = *(const float2*)(Bptr + (size_t)(kt + 1) * 8 * DMODEL);
        }
#pragma unroll
        for (int k = 0; k < 8; k++) {
            const u64t* a0 = (const u64t*)&As[k][ty * 4];
            const u64t* a1 = (const u64t*)&As[k][64 + ty * 4];
            u64t ap[4] = {a0[0], a0[1], a1[0], a1[1]};
            float4 b = *(const float4*)&Bs[k][tx * 4];
            u64t bb[4] = {f2pack(b.x, b.x), f2pack(b.y, b.y),
                          f2pack(b.z, b.z), f2pack(b.w, b.w)};
#pragma unroll
            for (int p = 0; p < 4; p++)
#pragma unroll
                for (int j = 0; j < 4; j++)
                    ffma2(accp[p][j], ap[p], bb[j]);
        }
        __syncthreads();
    }

    const int c = colBase + tx * 4;
    float4 bv = *(const float4*)&bias[c];
#pragma unroll
    for (int p = 0; p < 4; p++) {
        float lo[4], hi[4];
#pragma unroll
        for (int j = 0; j < 4; j++) f2unpack(lo[j], hi[j], accp[p][j]);
        int r0 = rowBase + ((p < 2) ? (ty * 4 + p * 2) : (64 + ty * 4 + (p - 2) * 2));
        float4 o0 = {lo[0] + bv.x, lo[1] + bv.y, lo[2] + bv.z, lo[3] + bv.w};
        float4 o1 = {hi[0] + bv.x, hi[1] + bv.y, hi[2] + bv.z, hi[3] + bv.w};
        *(float4*)&C[(size_t)r0 * DMODEL + c]       = o0;
        *(float4*)&C[(size_t)(r0 + 1) * DMODEL + c] = o1;
    }
}

// ---------------------------------------------------------------------------
// Scores (R9 exact): S = 0.125 * cur @ K^T per head. 128x128 tile, K=64.
// ---------------------------------------------------------------------------
__global__ __launch_bounds__(256)
void scores_kernel(const float* __restrict__ Qc, const float* __restrict__ Kc,
                   float* __restrict__ S)
{
    extern __shared__ float sm[];
    float (*As)[132] = (float(*)[132])sm;
    float (*Bs)[132] = (float(*)[132])(sm + 64 * 132);

    const int tid = threadIdx.x;
    const int tx = tid & 15;
    const int ty = tid >> 4;
    const int h = blockIdx.z;
    const int qBase = blockIdx.y * 128;
    const int kBase = blockIdx.x * 128;

    const float* Ap = Qc + (size_t)qBase * DMODEL + h * DKH;
    const float* Bp = Kc + (size_t)kBase * DMODEL + h * DKH;

#pragma unroll
    for (int i = 0; i < 8; i++) {
        int idx = tid + i * 256;
        int r   = idx >> 4;
        int c4  = (idx & 15) * 4;
        float4 a = *(const float4*)(Ap + (size_t)r * DMODEL + c4);
        As[c4 + 0][r] = a.x; As[c4 + 1][r] = a.y;
        As[c4 + 2][r] = a.z; As[c4 + 3][r] = a.w;
        float4 b = *(const float4*)(Bp + (size_t)r * DMODEL + c4);
        Bs[c4 + 0][r] = b.x; Bs[c4 + 1][r] = b.y;
        Bs[c4 + 2][r] = b.z; Bs[c4 + 3][r] = b.w;
    }
    __syncthreads();

    u64t accp[4][8];
#pragma unroll
    for (int p = 0; p < 4; p++)
#pragma unroll
        for (int j = 0; j < 8; j++) accp[p][j] = 0ull;

#pragma unroll 4
    for (int k = 0; k < 64; k++) {
        const u64t* a0 = (const u64t*)&As[k][ty * 4];
        const u64t* a1 = (const u64t*)&As[k][64 + ty * 4];
        u64t ap[4] = {a0[0], a0[1], a1[0], a1[1]};
        float4 b0 = *(const float4*)&Bs[k][tx * 4];
        float4 b1 = *(const float4*)&Bs[k][64 + tx * 4];
        u64t bb[8] = {f2pack(b0.x, b0.x), f2pack(b0.y, b0.y),
                      f2pack(b0.z, b0.z), f2pack(b0.w, b0.w),
                      f2pack(b1.x, b1.x), f2pack(b1.y, b1.y),
                      f2pack(b1.z, b1.z), f2pack(b1.w, b1.w)};
#pragma unroll
        for (int p = 0; p < 4; p++)
#pragma unroll
            for (int j = 0; j < 8; j++)
                ffma2(accp[p][j], ap[p], bb[j]);
    }

    const float sc = 0.125f;
    float* Sp = S + ((size_t)(h * LSEQ + qBase)) * LSEQ + kBase;
#pragma unroll
    for (int p = 0; p < 4; p++) {
        float lo[8], hi[8];
#pragma unroll
        for (int j = 0; j < 8; j++) f2unpack(lo[j], hi[j], accp[p][j]);
        int r0 = (p < 2) ? (ty * 4 + p * 2) : (64 + ty * 4 + (p - 2) * 2);
        float* d0 = &Sp[(size_t)r0 * LSEQ];
        float* d1 = &Sp[(size_t)(r0 + 1) * LSEQ];
        *(float4*)&d0[tx * 4] =
            make_float4(lo[0] * sc, lo[1] * sc, lo[2] * sc, lo[3] * sc);
        *(float4*)&d0[64 + tx * 4] =
            make_float4(lo[4] * sc, lo[5] * sc, lo[6] * sc, lo[7] * sc);
        *(float4*)&d1[tx * 4] =
            make_float4(hi[0] * sc, hi[1] * sc, hi[2] * sc, hi[3] * sc);
        *(float4*)&d1[64 + tx * 4] =
            make_float4(hi[4] * sc, hi[5] * sc, hi[6] * sc, hi[7] * sc);
    }
}

// ---------------------------------------------------------------------------
// Row stats: one warp per (h,q) row held in registers. Computes m, sum, then
// writes the FINAL gated weight w = exp(s-m) * gate/sum in place.
// ctx then becomes a pure GEMM (no second scale pass, no S re-write).
// ---------------------------------------------------------------------------
__global__ __launch_bounds__(256)
void stats_kernel(float* __restrict__ S)
{
    const int warp = threadIdx.x >> 5;
    const int lane = threadIdx.x & 31;
    const int row = blockIdx.x * 8 + warp;
    float* p = S + (size_t)row * LSEQ;

    float4 vals[16];
    float m = -1e30f;
#pragma unroll
    for (int i = 0; i < 16; i++) {
        vals[i] = *(const float4*)&p[(lane + i * 32) * 4];
        m = fmaxf(m, fmaxf(fmaxf(vals[i].x, vals[i].y), fmaxf(vals[i].z, vals[i].w)));
    }
#pragma unroll
    for (int off = 16; off > 0; off >>= 1)
        m = fmaxf(m, __shfl_xor_sync(0xffffffffu, m, off));

    float s = 0.f;
#pragma unroll
    for (int i = 0; i < 16; i++) {
        vals[i].x = __expf(vals[i].x - m);
        vals[i].y = __expf(vals[i].y - m);
        vals[i].z = __expf(vals[i].z - m);
        vals[i].w = __expf(vals[i].w - m);
        s += vals[i].x + vals[i].y + vals[i].z + vals[i].w;
    }
#pragma unroll
    for (int off = 16; off > 0; off >>= 1)
        s += __shfl_xor_sync(0xffffffffu, s, off);

    const float g = g_gate[row & (LSEQ - 1)] / s;
#pragma unroll
    for (int i = 0; i < 16; i++) {
        float4 w = {vals[i].x * g, vals[i].y * g, vals[i].z * g, vals[i].w * g};
        *(float4*)&p[(lane + i * 32) * 4] = w;
    }
}

// ---------------------------------------------------------------------------
// ctx = w @ V — pure GEMM (S already holds final w). R9 shape, minus the
// in-place S write and per-element scaling.
// ---------------------------------------------------------------------------
__global__ __launch_bounds__(256)
void ctx_kernel(const float* __restrict__ S, const float* __restrict__ V)
{
    __shared__ float Ws[32][132];
    __shared__ float Vs[32][64];

    const int tid = threadIdx.x;
    const int tx = tid & 15;
    const int ty = tid >> 4;
    const int h = blockIdx.y;
    const int qBase = blockIdx.x * 128;

    const int sRow0 = tid >> 3;
    const int sCol  = (tid & 7) * 4;

    const float* Sbase = S + ((size_t)(h * LSEQ + qBase)) * LSEQ;
    const float* Vp = V + h * DKH;

    u64t accp[4][4];
#pragma unroll
    for (int p = 0; p < 4; p++)
#pragma unroll
        for (int j = 0; j < 4; j++) accp[p][j] = 0ull;

    float4 sreg[4];
    float4 vreg[2];
#pragma unroll
    for (int r = 0; r < 4; r++)
        sreg[r] = *(const float4*)&Sbase[(size_t)(sRow0 + 32 * r) * LSEQ + sCol];
#pragma unroll
    for (int i = 0; i < 2; i++) {
        int idx = tid + i * 256;
        int vr = idx >> 4, vc = (idx & 15) * 4;
        vreg[i] = *(const float4*)&Vp[(size_t)vr * DMODEL + vc];
    }

    const int NT = LSEQ / 32;
    for (int kt = 0; kt < NT; kt++) {
#pragma unroll
        for (int r = 0; r < 4; r++) {
            int row = sRow0 + 32 * r;
            Ws[sCol + 0][row] = sreg[r].x; Ws[sCol + 1][row] = sreg[r].y;
            Ws[sCol + 2][row] = sreg[r].z; Ws[sCol + 3][row] = sreg[r].w;
        }
#pragma unroll
        for (int i = 0; i < 2; i++) {
            int idx = tid + i * 256;
            int vr = idx >> 4, vc = (idx & 15) * 4;
            *(float4*)&Vs[vr][vc] = vreg[i];
        }
        __syncthreads();
        if (kt + 1 < NT) {
#pragma unroll
            for (int r = 0; r < 4; r++)
                sreg[r] = *(const float4*)&Sbase[(size_t)(sRow0 + 32 * r) * LSEQ
                                                 + (kt + 1) * 32 + sCol];
#pragma unroll
            for (int i = 0; i < 2; i++) {
                int idx = tid + i * 256;
                int vr = idx >> 4, vc = (idx & 15) * 4;
                vreg[i] = *(const float4*)&Vp[(size_t)((kt + 1) * 32 + vr) * DMODEL + vc];
            }
        }
#pragma unroll 8
        for (int k = 0; k < 32; k++) {
            const u64t* a0 = (const u64t*)&Ws[k][ty * 4];
            const u64t* a1 = (const u64t*)&Ws[k][64 + ty * 4];
            u64t ap[4] = {a0[0], a0[1], a1[0], a1[1]};
            float4 b = *(const float4*)&Vs[k][tx * 4];
            u64t bb[4] = {f2pack(b.x, b.x), f2pack(b.y, b.y),
                          f2pack(b.z, b.z), f2pack(b.w, b.w)};
#pragma unroll
            for (int p = 0; p < 4; p++)
#pragma unroll
                for (int j = 0; j < 4; j++)
                    ffma2(accp[p][j], ap[p], bb[j]);
        }
        __syncthreads();
    }

#pragma unroll
    for (int p = 0; p < 4; p++) {
        float lo[4], hi[4];
#pragma unroll
        for (int j = 0; j < 4; j++) f2unpack(lo[j], hi[j], accp[p][j]);
        int r0 = qBase + ((p < 2) ? (ty * 4 + p * 2) : (64 + ty * 4 + (p - 2) * 2));
        *(float4*)&g_ctx[(size_t)r0 * DMODEL + h * DKH + tx * 4] =
            make_float4(lo[0], lo[1], lo[2], lo[3]);
        *(float4*)&g_ctx[(size_t)(r0 + 1) * DMODEL + h * DKH + tx * 4] =
            make_float4(hi[0], hi[1], hi[2], hi[3]);
    }
}

// ---------------------------------------------------------------------------
__global__ __launch_bounds__(256)
void gates_kernel(const float* __restrict__ q, const float* __restrict__ Wg,
                  const float* __restrict__ bg)
{
    const int warp = threadIdx.x >> 5;
    const int lane = threadIdx.x & 31;
    const int row = blockIdx.x * 8 + warp;
    const float* p = q + (size_t)row * DMODEL;

    float s = 0.f;
#pragma unroll
    for (int i = 0; i < 8; i++) {
        float4 a = *(const float4*)&p[(lane + i * 32) * 4];
        float4 w = *(const float4*)&Wg[(lane + i * 32) * 4];
        s += a.x * w.x + a.y * w.y + a.z * w.z + a.w * w.w;
    }
#pragma unroll
    for (int off = 16; off > 0; off >>= 1)
        s += __shfl_xor_sync(0xffffffffu, s, off);

    if (lane == 0)
        g_gate[row] = 1.f / (1.f + __expf(-(s + bg[0])));
}

// ---------------------------------------------------------------------------
extern "C" void kernel_launch(void* const* d_in, const int* in_sizes, int n_in,
                              void* d_out, int out_size)
{
    const float* q  = (const float*)d_in[0];
    const float* k  = (const float*)d_in[1];
    const float* v  = (const float*)d_in[2];
    const float* Wq = (const float*)d_in[3];
    const float* bq = (const float*)d_in[4];
    const float* Wk = (const float*)d_in[5];
    const float* bk = (const float*)d_in[6];
    const float* Wv = (const float*)d_in[7];
    const float* bv = (const float*)d_in[8];
    const float* Wo = (const float*)d_in[9];
    const float* bo = (const float*)d_in[10];
    const float* Wg = (const float*)d_in[11];
    const float* bg = (const float*)d_in[12];
    const float* Wp = (const float*)d_in[13];
    const float* bp = (const float*)d_in[14];
    (void)in_sizes; (void)n_in; (void)out_size;

    float* out  = (float*)d_out;                          // (L, D)
    float* Wout = out + (size_t)LSEQ * DMODEL;            // (3, H, L, L)

    float *pQ, *pK, *pV, *pCtx, *pCur;
    cudaGetSymbolAddress((void**)&pQ,   g_Q);
    cudaGetSymbolAddress((void**)&pK,   g_K);
    cudaGetSymbolAddress((void**)&pV,   g_V);
    cudaGetSymbolAddress((void**)&pCtx, g_ctx);
    cudaGetSymbolAddress((void**)&pCur, g_cur);

    const size_t smemScores = 2 * 64 * 132 * sizeof(float);  // 67.6 KB
    cudaFuncSetAttribute(scores_kernel,
                         cudaFuncAttributeMaxDynamicSharedMemorySize,
                         (int)smemScores);

    dim3 gProj(DMODEL / 64, LSEQ / 128);  // (16, 16)

    gates_kernel<<<LSEQ / 8, 256>>>(q, Wg, bg);
    gemm_proj<<<gProj, 256>>>(q, Wq, bq, pQ);
    gemm_proj<<<gProj, 256>>>(k, Wk, bk, pK);
    gemm_proj<<<gProj, 256>>>(v, Wv, bv, pV);

    const float* cur = pQ;
    for (int hop = 0; hop < NHOPS; hop++) {
        float* Sh = Wout + (size_t)hop * NH * LSEQ * LSEQ;
        dim3 gS(LSEQ / 128, LSEQ / 128, NH);
        scores_kernel<<<gS, 256, smemScores>>>(cur, pK, Sh);
        stats_kernel<<<NH * LSEQ / 8, 256>>>(Sh);
        dim3 gC(LSEQ / 128, NH);
        ctx_kernel<<<gC, 256>>>(Sh, pV);
        if (hop < NHOPS - 1) {
            gemm_proj<<<gProj, 256>>>(pCtx, Wp, bp, pCur);
            cur = pCur;
        }
    }
    gemm_proj<<<gProj, 256>>>(pCtx, Wo, bo, out);
}